// round 13
// baseline (speedup 1.0000x reference)
#include <cuda_runtime.h>
#include <cstdint>

#define Bsz 8
#define Nn 5000
#define NG 3                 // node-groups per block (fully unrolled)
#define NODES (6 * NG)       // 18 nodes per block
#define THREADS 192          // 6 warps, one node per warp per group

// smem layout in 4B units
#define U_W    0             // 5 * 2048 (all five weights, fp16 frag layout)
#define U_BIAS 10240         // 320 f32
#define U_TOT  10560         // 42,240 B

typedef unsigned long long u64;

// ---------------- helpers ----------------
__device__ __forceinline__ unsigned ph2(float x, float y) {   // lo = x, hi = y
    unsigned r;
    asm("cvt.rn.f16x2.f32 %0, %1, %2;" : "=r"(r) : "f"(y), "f"(x));
    return r;
}
__device__ __forceinline__ void ld_pair(const unsigned* p, unsigned& lo, unsigned& hi) {
    const u64 v = *(const u64*)p;
    lo = (unsigned)v; hi = (unsigned)(v >> 32);
}
__device__ __forceinline__ int posj(int jj) { return ((jj & 3) << 1) | (jj >> 2); }

__device__ __forceinline__ void mma16(float d[4], const unsigned a[4],
                                      unsigned b0, unsigned b1) {
    asm volatile(
        "mma.sync.aligned.m16n8k16.row.col.f32.f16.f16.f32 "
        "{%0,%1,%2,%3}, {%4,%5,%6,%7}, {%8,%9}, {%0,%1,%2,%3};"
        : "+f"(d[0]), "+f"(d[1]), "+f"(d[2]), "+f"(d[3])
        : "r"(a[0]), "r"(a[1]), "r"(a[2]), "r"(a[3]), "r"(b0), "r"(b1));
}
__device__ __forceinline__ void mma8(float d[4], unsigned a0, unsigned a1, unsigned b0) {
    asm volatile(
        "mma.sync.aligned.m16n8k8.row.col.f32.f16.f16.f32 "
        "{%0,%1,%2,%3}, {%4,%5}, {%6}, {%0,%1,%2,%3};"
        : "+f"(d[0]), "+f"(d[1]), "+f"(d[2]), "+f"(d[3])
        : "r"(a0), "r"(a1), "r"(b0));
}

// ---------------- kernel ----------------
__global__ void __launch_bounds__(THREADS, 3)
fused_dreg_kernel(const float* __restrict__ X,
                  const float* __restrict__ STE_P,
                  const float* __restrict__ STE_Q,
                  const float* __restrict__ W21, const float* __restrict__ b21,
                  const float* __restrict__ W22, const float* __restrict__ b22,
                  const float* __restrict__ W23, const float* __restrict__ b23,
                  const float* __restrict__ W24, const float* __restrict__ b24,
                  const float* __restrict__ W25, const float* __restrict__ b25,
                  float* __restrict__ Out)
{
    extern __shared__ unsigned sm[];
    unsigned* sW = sm + U_W;
    float*    sBias = (float*)(sm + U_BIAS);

    const int tid  = threadIdx.x;
    const int w    = tid >> 5;
    const int lane = tid & 31;
    const int gid  = lane >> 2;
    const int tig  = lane & 3;
    const int g3   = gid & 3;
    const int b    = blockIdx.y;
    const int n0   = blockIdx.x * NODES;

    // global row bases for direct a-frag loads (t = gid and t = gid + 8)
    const int ro0 = ((b * 12 + gid) * Nn + (n0 + w)) * 64 + 2 * tig;
    const int ro1 = ro0 + 8 * Nn * 64;

    unsigned fA[4][4], fB[4][4];

// direct a-frag load from global: buf[kc] = frags of rows (t=gid, t=gid+8)
#define LDGF(src, goff, buf, vld)                                           \
    {                                                                       \
        if (vld) {                                                          \
            _Pragma("unroll")                                               \
            for (int kc = 0; kc < 4; kc++) {                                \
                const float2 v0 = *(const float2*)((src) + ro0 + (goff) + 16 * kc);     \
                const float2 v1 = *(const float2*)((src) + ro0 + (goff) + 16 * kc + 8); \
                (buf)[kc][0] = ph2(v0.x, v0.y);                             \
                (buf)[kc][2] = ph2(v1.x, v1.y);                             \
            }                                                               \
            if (gid < 4) {                                                  \
                _Pragma("unroll")                                           \
                for (int kc = 0; kc < 4; kc++) {                            \
                    const float2 v0 = *(const float2*)((src) + ro1 + (goff) + 16 * kc);     \
                    const float2 v1 = *(const float2*)((src) + ro1 + (goff) + 16 * kc + 8); \
                    (buf)[kc][1] = ph2(v0.x, v0.y);                         \
                    (buf)[kc][3] = ph2(v1.x, v1.y);                         \
                }                                                           \
            } else {                                                        \
                _Pragma("unroll")                                           \
                for (int kc = 0; kc < 4; kc++) { (buf)[kc][1] = 0u; (buf)[kc][3] = 0u; } \
            }                                                               \
        } else {                                                            \
            _Pragma("unroll")                                               \
            for (int kc = 0; kc < 4; kc++) {                                \
                (buf)[kc][0] = 0u; (buf)[kc][1] = 0u;                       \
                (buf)[kc][2] = 0u; (buf)[kc][3] = 0u;                       \
            }                                                               \
        }                                                                   \
    }

    // issue group-0 STE_Q loads FIRST (overlap with weight staging)
    LDGF(STE_Q, 0, fA, (n0 + w) < Nn);

    if (tid < 64) {
        sBias[tid]       = b21[tid];
        sBias[64 + tid]  = b22[tid];
        sBias[128 + tid] = b23[tid];
        sBias[192 + tid] = b24[tid];
        sBias[256 + tid] = b25[tid];
    }
    // stage all five weights once (fp16 frag layout)
    {
        const float* Ws[5] = { W21, W22, W23, W24, W25 };
#pragma unroll
        for (int s = 0; s < 5; s++) {
            unsigned* dw = sW + s * 2048;
#pragma unroll
            for (int it = 0; it < 6; it++) {
                const int idx = tid + it * THREADS;
                if (idx < 1024) {
                    const int n = idx >> 4, c4 = idx & 15;
                    const float4 v = *(const float4*)(Ws[s] + n * 64 + c4 * 4);
                    const int a0 = n * 32 + (((c4 >> 2) ^ (n & 3)) << 3)
                                   + posj((2 * c4) & 7);
                    dw[a0]     = ph2(v.x, v.y);
                    dw[a0 + 2] = ph2(v.z, v.w);
                }
            }
        }
    }
    __syncthreads();                                     // the ONLY block sync

    unsigned qa[8][2], kb[8][2], vb[8][2], oa[8][2], ha[8][2];
    const float scale = 0.35355339059327373f;            // 1/sqrt(8), folded into Q

#define GEMM_PACK(buf, wsel, boff, mult, dst)                               \
    {                                                                       \
        _Pragma("unroll")                                                   \
        for (int nt = 0; nt < 8; nt++) {                                    \
            float dd[4] = {0.f, 0.f, 0.f, 0.f};                             \
            const unsigned* wr = sW + (wsel) * 2048 + (nt * 8 + gid) * 32;  \
            _Pragma("unroll")                                               \
            for (int kc = 0; kc < 4; kc++) {                                \
                unsigned b0, b1;                                            \
                ld_pair(wr + ((kc ^ g3) << 3) + 2 * tig, b0, b1);           \
                mma16(dd, (buf)[kc], b0, b1);                               \
            }                                                               \
            const float2 bc = *(const float2*)(sBias + (boff) + nt * 8 + 2 * tig); \
            (dst)[nt][0] = ph2(fmaxf(dd[0] + bc.x, 0.f) * (mult),           \
                               fmaxf(dd[1] + bc.y, 0.f) * (mult));          \
            (dst)[nt][1] = ph2(fmaxf(dd[2] + bc.x, 0.f) * (mult),           \
                               fmaxf(dd[3] + bc.y, 0.f) * (mult));          \
        }                                                                   \
    }

// phase C: Vt = relu(W23 * X^T + b23) ; X a-frags reused as B-operand from regs
#define PHASE_C(buf)                                                        \
    {                                                                       \
        _Pragma("unroll")                                                   \
        for (int mt = 0; mt < 4; mt++) {                                    \
            const float bj0 = sBias[128 + 16 * mt + gid];                   \
            const float bj1 = sBias[128 + 16 * mt + 8 + gid];               \
            float d0[4] = {0.f, 0.f, 0.f, 0.f};                             \
            float d1[4] = {0.f, 0.f, 0.f, 0.f};                             \
            _Pragma("unroll")                                               \
            for (int kc = 0; kc < 4; kc++) {                                \
                const int off = ((kc ^ g3) << 3) + 2 * tig;                 \
                unsigned wa[4];                                             \
                ld_pair(sW + 2 * 2048 + (16 * mt + gid) * 32 + off, wa[0], wa[2]); \
                ld_pair(sW + 2 * 2048 + (16 * mt + 8 + gid) * 32 + off, wa[1], wa[3]); \
                mma16(d0, wa, (buf)[kc][0], (buf)[kc][2]);                  \
                mma16(d1, wa, (buf)[kc][1], (buf)[kc][3]);                  \
            }                                                               \
            vb[2 * mt][0]     = ph2(fmaxf(d0[0] + bj0, 0.f), fmaxf(d0[1] + bj0, 0.f)); \
            vb[2 * mt][1]     = ph2(fmaxf(d1[0] + bj0, 0.f), fmaxf(d1[1] + bj0, 0.f)); \
            vb[2 * mt + 1][0] = ph2(fmaxf(d0[2] + bj1, 0.f), fmaxf(d0[3] + bj1, 0.f)); \
            vb[2 * mt + 1][1] = ph2(fmaxf(d1[2] + bj1, 0.f), fmaxf(d1[3] + bj1, 0.f)); \
        }                                                                   \
    }

#define GEMM_REG(wsel, src, nt, dd)                                         \
    {                                                                       \
        const unsigned* wr = sW + (wsel) * 2048 + ((nt) * 8 + gid) * 32;    \
        _Pragma("unroll")                                                   \
        for (int kc = 0; kc < 4; kc++) {                                    \
            unsigned aR[4] = { (src)[2 * kc][0], (src)[2 * kc][1],          \
                               (src)[2 * kc + 1][0], (src)[2 * kc + 1][1] };\
            unsigned b0, b1;                                                \
            ld_pair(wr + ((kc ^ g3) << 3) + 2 * tig, b0, b1);               \
            mma16(dd, aR, b0, b1);                                          \
        }                                                                   \
    }

#define ATTENTION()                                                         \
    {                                                                       \
        _Pragma("unroll")                                                   \
        for (int h = 0; h < 8; h++) {                                       \
            float s1[4] = {0.f, 0.f, 0.f, 0.f};                             \
            float s2[4] = {0.f, 0.f, 0.f, 0.f};                             \
            mma8(s1, qa[h][0], qa[h][1], kb[h][0]);                         \
            mma8(s2, qa[h][0], qa[h][1], kb[h][1]);                         \
            const float e10 = __expf(s1[0] - 8.f), e11 = __expf(s1[1] - 8.f); \
            const float e12 = __expf(s1[2] - 8.f), e13 = __expf(s1[3] - 8.f); \
            float e20 = 0.f, e21 = 0.f, e22 = 0.f, e23 = 0.f;               \
            if (tig < 2) {                                                  \
                e20 = __expf(s2[0] - 8.f); e21 = __expf(s2[1] - 8.f);       \
                e22 = __expf(s2[2] - 8.f); e23 = __expf(s2[3] - 8.f);       \
            }                                                               \
            float sumA = e10 + e11 + e20 + e21;                             \
            float sumB = e12 + e13 + e22 + e23;                             \
            sumA += __shfl_xor_sync(0xffffffffu, sumA, 1);                  \
            sumA += __shfl_xor_sync(0xffffffffu, sumA, 2);                  \
            sumB += __shfl_xor_sync(0xffffffffu, sumB, 1);                  \
            sumB += __shfl_xor_sync(0xffffffffu, sumB, 2);                  \
            const float invA = __fdividef(1.f, sumA);                       \
            const float invB = __fdividef(1.f, sumB);                       \
            unsigned pa[4];                                                 \
            pa[0] = ph2(e10 * invA, e11 * invA);                            \
            pa[1] = ph2(e12 * invB, e13 * invB);                            \
            pa[2] = ph2(e20 * invA, e21 * invA);                            \
            pa[3] = ph2(e22 * invB, e23 * invB);                            \
            float ov[4] = {0.f, 0.f, 0.f, 0.f};                             \
            mma16(ov, pa, vb[h][0], vb[h][1]);                              \
            oa[h][0] = ph2(ov[0], ov[1]);                                   \
            oa[h][1] = ph2(ov[2], ov[3]);                                   \
        }                                                                   \
    }

#define PHASE_DE(node, valid)                                               \
    {                                                                       \
        _Pragma("unroll")                                                   \
        for (int nt = 0; nt < 8; nt++) {                                    \
            float dd[4] = {0.f, 0.f, 0.f, 0.f};                             \
            GEMM_REG(3, oa, nt, dd);                                        \
            const float2 bc = *(const float2*)(sBias + 192 + nt * 8 + 2 * tig); \
            ha[nt][0] = ph2(fmaxf(dd[0] + bc.x, 0.f), fmaxf(dd[1] + bc.y, 0.f)); \
            ha[nt][1] = ph2(fmaxf(dd[2] + bc.x, 0.f), fmaxf(dd[3] + bc.y, 0.f)); \
        }                                                                   \
        float* o0 = Out + ((size_t)(b * 12 + gid) * Nn + (node)) * 64;      \
        float* o1 = Out + ((size_t)(b * 12 + gid + 8) * Nn + (node)) * 64;  \
        _Pragma("unroll")                                                   \
        for (int nt = 0; nt < 8; nt++) {                                    \
            float dd[4] = {0.f, 0.f, 0.f, 0.f};                             \
            GEMM_REG(4, ha, nt, dd);                                        \
            const float2 bc = *(const float2*)(sBias + 256 + nt * 8 + 2 * tig); \
            if (valid) {                                                    \
                *(float2*)(o0 + nt * 8 + 2 * tig) =                         \
                    make_float2(dd[0] + bc.x, dd[1] + bc.y);                \
                if (gid < 4)                                                \
                    *(float2*)(o1 + nt * 8 + 2 * tig) =                     \
                        make_float2(dd[2] + bc.x, dd[3] + bc.y);            \
            }                                                               \
        }                                                                   \
    }

// one group: CUR holds this group's STE_Q frags on entry; NXT gets next group's
#define GROUP(CUR, NXT, G, LAST)                                            \
    {                                                                       \
        const int node = n0 + 6 * (G) + w;                                  \
        const bool valid = (node < Nn);                                     \
        const bool validn = (!(LAST)) && (node + 6 < Nn);                   \
        /* A: prefetch STE_P -> NXT ; GEMM qa from CUR */                   \
        LDGF(STE_P, (G) * 384, NXT, valid);                                 \
        GEMM_PACK(CUR, 0, 0, scale, qa);                                    \
        /* B: prefetch X -> CUR (CUR dead after GEMM A) ; GEMM kb from NXT */\
        LDGF(X, (G) * 384, CUR, valid);                                     \
        GEMM_PACK(NXT, 1, 64, 1.f, kb);                                     \
        /* C: prefetch next STE_Q -> NXT ; Vt from CUR (X frags) */         \
        LDGF(STE_Q, (G) * 384 + 384, NXT, validn);                          \
        PHASE_C(CUR);                                                       \
        ATTENTION();                                                        \
        PHASE_DE(node, valid);                                              \
    }

    GROUP(fA, fB, 0, false);
    GROUP(fB, fA, 1, false);
    GROUP(fA, fB, 2, true);

#undef LDGF
#undef GEMM_PACK
#undef PHASE_C
#undef GEMM_REG
#undef ATTENTION
#undef PHASE_DE
#undef GROUP
}

extern "C" void kernel_launch(void* const* d_in, const int* in_sizes, int n_in,
                              void* d_out, int out_size)
{
    const float* X     = (const float*)d_in[0];
    const float* STE_P = (const float*)d_in[1];
    const float* STE_Q = (const float*)d_in[2];
    const float* W21   = (const float*)d_in[3];
    const float* b21   = (const float*)d_in[4];
    const float* W22   = (const float*)d_in[5];
    const float* b22   = (const float*)d_in[6];
    const float* W23   = (const float*)d_in[7];
    const float* b23   = (const float*)d_in[8];
    const float* W24   = (const float*)d_in[9];
    const float* b24   = (const float*)d_in[10];
    const float* W25   = (const float*)d_in[11];
    const float* b25   = (const float*)d_in[12];
    float* Out = (float*)d_out;

    const size_t smem_bytes = (size_t)U_TOT * 4;          // 42,240 B

    cudaFuncSetAttribute(fused_dreg_kernel,
                         cudaFuncAttributeMaxDynamicSharedMemorySize,
                         (int)smem_bytes);

    dim3 grid((Nn + NODES - 1) / NODES, Bsz);             // (278, 8) = 2224 CTAs
    fused_dreg_kernel<<<grid, THREADS, smem_bytes>>>(
        X, STE_P, STE_Q,
        W21, b21, W22, b22, W23, b23, W24, b24, W25, b25,
        Out);
}

// round 14
// speedup vs baseline: 1.5091x; 1.5091x over previous
#include <cuda_runtime.h>
#include <cstdint>

#define Bsz 8
#define Nn 5000
#define NG 5                 // node-groups per block
#define NODES (6 * NG)       // 30 nodes per block
#define THREADS 192          // 6 warps = 3 pairs; pair handles 2 nodes, N split by warp

// smem layout in 4B units
#define U_W    0             // 5 * 2048 weights (fp16 frag layout)
#define U_BIAS 10240         // 320 f32
#define U_SLAB 10560         // 96 rows * 32 u  (input staging)
#define U_EXCH 13632         // 6 warps * 16 idx * 32 lanes
#define U_TOT  16704         // 66,816 B -> 3 CTAs/SM

typedef unsigned long long u64;

__device__ __forceinline__ unsigned ph2(float x, float y) {   // lo=x, hi=y
    unsigned r;
    asm("cvt.rn.f16x2.f32 %0, %1, %2;" : "=r"(r) : "f"(y), "f"(x));
    return r;
}
__device__ __forceinline__ void ld_pair(const unsigned* p, unsigned& lo, unsigned& hi) {
    const u64 v = *(const u64*)p;
    lo = (unsigned)v; hi = (unsigned)(v >> 32);
}
__device__ __forceinline__ int posj(int jj) { return ((jj & 3) << 1) | (jj >> 2); }

__device__ __forceinline__ void mma16(float d[4], const unsigned a[4],
                                      unsigned b0, unsigned b1) {
    asm volatile(
        "mma.sync.aligned.m16n8k16.row.col.f32.f16.f16.f32 "
        "{%0,%1,%2,%3}, {%4,%5,%6,%7}, {%8,%9}, {%0,%1,%2,%3};"
        : "+f"(d[0]), "+f"(d[1]), "+f"(d[2]), "+f"(d[3])
        : "r"(a[0]), "r"(a[1]), "r"(a[2]), "r"(a[3]), "r"(b0), "r"(b1));
}
__device__ __forceinline__ void mma8(float d[4], unsigned a0, unsigned a1, unsigned b0) {
    asm volatile(
        "mma.sync.aligned.m16n8k8.row.col.f32.f16.f16.f32 "
        "{%0,%1,%2,%3}, {%4,%5}, {%6}, {%0,%1,%2,%3};"
        : "+f"(d[0]), "+f"(d[1]), "+f"(d[2]), "+f"(d[3])
        : "r"(a0), "r"(a1), "r"(b0));
}

__global__ void __launch_bounds__(THREADS, 3)
fused_pair_kernel(const float* __restrict__ X,
                  const float* __restrict__ STE_P,
                  const float* __restrict__ STE_Q,
                  const float* __restrict__ W21, const float* __restrict__ b21,
                  const float* __restrict__ W22, const float* __restrict__ b22,
                  const float* __restrict__ W23, const float* __restrict__ b23,
                  const float* __restrict__ W24, const float* __restrict__ b24,
                  const float* __restrict__ W25, const float* __restrict__ b25,
                  float* __restrict__ Out)
{
    extern __shared__ unsigned sm[];
    unsigned* sW    = sm + U_W;
    float*    sBias = (float*)(sm + U_BIAS);
    unsigned* slab  = sm + U_SLAB;
    unsigned* exch  = sm + U_EXCH;

    const int tid  = threadIdx.x;
    const int w    = tid >> 5;
    const int lane = tid & 31;
    const int gid  = lane >> 2;
    const int tig  = lane & 3;
    const int g3   = gid & 3;
    const int pair = w >> 1;
    const int hh   = w & 1;          // N-half: cols [32hh, 32hh+32)
    const int pw   = w ^ 1;          // partner warp
    const int jm0  = 2 * pair;       // slab slots / node offsets within group
    const int b    = blockIdx.y;
    const int n0   = blockIdx.x * NODES;

#define PAIRBAR() asm volatile("bar.sync %0, %1;" :: "r"(pair + 1), "r"(64) : "memory")

    // staging indices: warp w stages node (group_base + w) into slab slot w
    int gof[6], sap[6];
#pragma unroll
    for (int i = 0; i < 6; i++) {
        const int idx = lane + 32 * i;
        const int row = idx >> 4, c4 = idx & 15;
        gof[i] = ((b * 12 + row) * Nn + (n0 + w)) * 64 + c4 * 4;
        sap[i] = (16 * w + row) * 32 + (((c4 >> 2) ^ (row & 3)) << 3)
                 + posj((2 * c4) & 7);
    }

    if (tid < 64) {
        sBias[tid]       = b21[tid];
        sBias[64 + tid]  = b22[tid];
        sBias[128 + tid] = b23[tid];
        sBias[192 + tid] = b24[tid];
        sBias[256 + tid] = b25[tid];
    }
    {
        const float* Ws[5] = { W21, W22, W23, W24, W25 };
#pragma unroll
        for (int s = 0; s < 5; s++) {
            unsigned* dw = sW + s * 2048;
#pragma unroll
            for (int it = 0; it < 6; it++) {
                const int idx = tid + it * THREADS;
                if (idx < 1024) {
                    const int n = idx >> 4, c4 = idx & 15;
                    const float4 v = *(const float4*)(Ws[s] + n * 64 + c4 * 4);
                    const int a0 = n * 32 + (((c4 >> 2) ^ (n & 3)) << 3)
                                   + posj((2 * c4) & 7);
                    dw[a0]     = ph2(v.x, v.y);
                    dw[a0 + 2] = ph2(v.z, v.w);
                }
            }
        }
    }
    // zero pad rows 12-15 of slab slot w (stay zero forever)
    ((uint4*)(slab + (16 * w + 12) * 32))[lane] = make_uint4(0, 0, 0, 0);

    // stage group-0 STE_Q
    if (n0 + w < Nn) {
#pragma unroll
        for (int i = 0; i < 6; i++) {
            const float4 v = *(const float4*)(STE_Q + gof[i]);
            slab[sap[i]]     = ph2(v.x, v.y);
            slab[sap[i] + 2] = ph2(v.z, v.w);
        }
    }
    __syncthreads();

    uint2 hx[6];
#define PREFETCH(src, go, vld)                                              \
    if (vld) {                                                              \
        _Pragma("unroll")                                                   \
        for (int i = 0; i < 6; i++) {                                       \
            const float4 v = *(const float4*)((src) + gof[i] + (go));       \
            hx[i].x = ph2(v.x, v.y);                                        \
            hx[i].y = ph2(v.z, v.w);                                        \
        }                                                                   \
    }
#define STS_IN(vld)                                                         \
    if (vld) {                                                              \
        _Pragma("unroll")                                                   \
        for (int i = 0; i < 6; i++) {                                       \
            slab[sap[i]]     = hx[i].x;                                     \
            slab[sap[i] + 2] = hx[i].y;                                     \
        }                                                                   \
    }
// load A-frags for BOTH pair nodes from slab slots jm0, jm0+1
#define LOADF2()                                                            \
    {                                                                       \
        _Pragma("unroll")                                                   \
        for (int kc = 0; kc < 4; kc++) {                                    \
            const int off = ((kc ^ g3) << 3) + 2 * tig;                     \
            ld_pair(slab + (16 * jm0 + gid) * 32 + off,      fa0[kc][0], fa0[kc][2]); \
            ld_pair(slab + (16 * jm0 + 8 + gid) * 32 + off,  fa0[kc][1], fa0[kc][3]); \
            ld_pair(slab + (16 * jm0 + 16 + gid) * 32 + off, fa1[kc][0], fa1[kc][2]); \
            ld_pair(slab + (16 * jm0 + 24 + gid) * 32 + off, fa1[kc][1], fa1[kc][3]); \
        }                                                                   \
    }
// half-N GEMM for both nodes, weights shared: nt' 0..3 -> global nt 4hh+nt'
#define GEMM_AB(wsel, boff, mult, dst)                                      \
    {                                                                       \
        _Pragma("unroll")                                                   \
        for (int ntp = 0; ntp < 4; ntp++) {                                 \
            const int ntg = 4 * hh + ntp;                                   \
            float dA[4] = {0.f, 0.f, 0.f, 0.f};                             \
            float dB[4] = {0.f, 0.f, 0.f, 0.f};                             \
            const unsigned* wr = sW + (wsel) * 2048 + (ntg * 8 + gid) * 32; \
            _Pragma("unroll")                                               \
            for (int kc = 0; kc < 4; kc++) {                                \
                unsigned b0, b1;                                            \
                ld_pair(wr + ((kc ^ g3) << 3) + 2 * tig, b0, b1);           \
                mma16(dA, fa0[kc], b0, b1);                                 \
                mma16(dB, fa1[kc], b0, b1);                                 \
            }                                                               \
            const float2 bc = *(const float2*)(sBias + (boff) + ntg * 8 + 2 * tig); \
            (dst)[0][ntp][0] = ph2(fmaxf(dA[0] + bc.x, 0.f) * (mult),       \
                                   fmaxf(dA[1] + bc.y, 0.f) * (mult));      \
            (dst)[0][ntp][1] = ph2(fmaxf(dA[2] + bc.x, 0.f) * (mult),       \
                                   fmaxf(dA[3] + bc.y, 0.f) * (mult));      \
            (dst)[1][ntp][0] = ph2(fmaxf(dB[0] + bc.x, 0.f) * (mult),       \
                                   fmaxf(dB[1] + bc.y, 0.f) * (mult));      \
            (dst)[1][ntp][1] = ph2(fmaxf(dB[2] + bc.x, 0.f) * (mult),       \
                                   fmaxf(dB[3] + bc.y, 0.f) * (mult));      \
        }                                                                   \
    }

    unsigned fa0[4][4], fa1[4][4];
    unsigned qa[2][4][2], kb[2][4][2], vb[2][4][2], oa[2][4][2], ha[2][4][2];
    unsigned ofu[2][4][4];           // full-K A-frags (own + partner halves)
    const float scale = 0.35355339059327373f;

#pragma unroll 1
    for (int g = 0; g < NG; g++) {
        const int nodeS = n0 + 6 * g + w;        // staged node
        const bool vS   = (nodeS < Nn);
        const bool vSn  = (g + 1 < NG) && (nodeS + 6 < Nn);
        const int node0 = n0 + 6 * g + jm0;
        const bool v0   = (node0 < Nn);
        const bool v1   = (node0 + 1 < Nn);

        // ---- phase A: Q (scaled) ----
        PREFETCH(STE_P, 0, vS);
        LOADF2();
        GEMM_AB(0, 0, scale, qa);
        PAIRBAR();                 // partner done reading Q slab
        STS_IN(vS);                // STE_P
        PAIRBAR();                 // P visible

        // ---- phase B: K ----
        PREFETCH(X, 0, vS);
        LOADF2();
        GEMM_AB(1, 64, 1.f, kb);
        PAIRBAR();
        STS_IN(vS);                // X
        PAIRBAR();                 // X visible

        // ---- phase C (transposed): Vt half = rows [32hh,+32) of W23 * X^T ----
        PREFETCH(STE_Q, 384, vSn); // next group's Q
        {
            float dc[2][2][8];     // [m][mt'][0..3 = times0-7, 4..7 = times8-15]
#pragma unroll
            for (int m = 0; m < 2; m++)
#pragma unroll
                for (int mt = 0; mt < 2; mt++)
#pragma unroll
                    for (int e = 0; e < 8; e++) dc[m][mt][e] = 0.f;
#pragma unroll
            for (int kc = 0; kc < 4; kc++) {
                const int off = ((kc ^ g3) << 3) + 2 * tig;
                unsigned x00, x01, x02, x03, x10, x11, x12, x13;
                ld_pair(slab + (16 * jm0 + gid) * 32 + off,      x00, x01);
                ld_pair(slab + (16 * jm0 + 8 + gid) * 32 + off,  x02, x03);
                ld_pair(slab + (16 * jm0 + 16 + gid) * 32 + off, x10, x11);
                ld_pair(slab + (16 * jm0 + 24 + gid) * 32 + off, x12, x13);
#pragma unroll
                for (int mt = 0; mt < 2; mt++) {
                    unsigned wa[4];
                    const int rb = 32 * hh + 16 * mt;
                    ld_pair(sW + 2 * 2048 + (rb + gid) * 32 + off,     wa[0], wa[2]);
                    ld_pair(sW + 2 * 2048 + (rb + 8 + gid) * 32 + off, wa[1], wa[3]);
                    mma16(&dc[0][mt][0], wa, x00, x01);
                    mma16(&dc[0][mt][4], wa, x02, x03);
                    mma16(&dc[1][mt][0], wa, x10, x11);
                    mma16(&dc[1][mt][4], wa, x12, x13);
                }
            }
#pragma unroll
            for (int m = 0; m < 2; m++)
#pragma unroll
            for (int mt = 0; mt < 2; mt++) {
                const float bj0 = sBias[128 + 32 * hh + 16 * mt + gid];
                const float bj1 = sBias[128 + 32 * hh + 16 * mt + 8 + gid];
                vb[m][2 * mt][0]     = ph2(fmaxf(dc[m][mt][0] + bj0, 0.f),
                                           fmaxf(dc[m][mt][1] + bj0, 0.f));
                vb[m][2 * mt][1]     = ph2(fmaxf(dc[m][mt][4] + bj0, 0.f),
                                           fmaxf(dc[m][mt][5] + bj0, 0.f));
                vb[m][2 * mt + 1][0] = ph2(fmaxf(dc[m][mt][2] + bj1, 0.f),
                                           fmaxf(dc[m][mt][3] + bj1, 0.f));
                vb[m][2 * mt + 1][1] = ph2(fmaxf(dc[m][mt][6] + bj1, 0.f),
                                           fmaxf(dc[m][mt][7] + bj1, 0.f));
            }
        }
        PAIRBAR();                 // C slab reads done
        STS_IN(vSn);               // next group's Q (ordered by later bars)

        // ---- attention: 4 own heads per node, register-local ----
#pragma unroll
        for (int m = 0; m < 2; m++) {
#pragma unroll
            for (int h = 0; h < 4; h++) {
                float s1[4] = {0.f, 0.f, 0.f, 0.f};
                float s2[4] = {0.f, 0.f, 0.f, 0.f};
                mma8(s1, qa[m][h][0], qa[m][h][1], kb[m][h][0]);
                mma8(s2, qa[m][h][0], qa[m][h][1], kb[m][h][1]);
                const float e10 = __expf(s1[0] - 8.f), e11 = __expf(s1[1] - 8.f);
                const float e12 = __expf(s1[2] - 8.f), e13 = __expf(s1[3] - 8.f);
                float e20 = 0.f, e21 = 0.f, e22 = 0.f, e23 = 0.f;
                if (tig < 2) {
                    e20 = __expf(s2[0] - 8.f); e21 = __expf(s2[1] - 8.f);
                    e22 = __expf(s2[2] - 8.f); e23 = __expf(s2[3] - 8.f);
                }
                float sumA = e10 + e11 + e20 + e21;
                float sumB = e12 + e13 + e22 + e23;
                sumA += __shfl_xor_sync(0xffffffffu, sumA, 1);
                sumA += __shfl_xor_sync(0xffffffffu, sumA, 2);
                sumB += __shfl_xor_sync(0xffffffffu, sumB, 1);
                sumB += __shfl_xor_sync(0xffffffffu, sumB, 2);
                const float invA = __fdividef(1.f, sumA);
                const float invB = __fdividef(1.f, sumB);
                unsigned pa[4];
                pa[0] = ph2(e10 * invA, e11 * invA);
                pa[1] = ph2(e12 * invB, e13 * invB);
                pa[2] = ph2(e20 * invA, e21 * invA);
                pa[3] = ph2(e22 * invB, e23 * invB);
                float ov[4] = {0.f, 0.f, 0.f, 0.f};
                mma16(ov, pa, vb[m][h][0], vb[m][h][1]);
                oa[m][h][0] = ph2(ov[0], ov[1]);
                oa[m][h][1] = ph2(ov[2], ov[3]);
            }
        }

        // ---- exchange O halves ----
#pragma unroll
        for (int m = 0; m < 2; m++)
#pragma unroll
            for (int h = 0; h < 4; h++) {
                exch[(w * 16 + m * 8 + h * 2 + 0) * 32 + lane] = oa[m][h][0];
                exch[(w * 16 + m * 8 + h * 2 + 1) * 32 + lane] = oa[m][h][1];
            }
        PAIRBAR();
#pragma unroll
        for (int m = 0; m < 2; m++) {
            if (hh == 0) {
                ofu[m][0][0] = oa[m][0][0]; ofu[m][0][1] = oa[m][0][1];
                ofu[m][0][2] = oa[m][1][0]; ofu[m][0][3] = oa[m][1][1];
                ofu[m][1][0] = oa[m][2][0]; ofu[m][1][1] = oa[m][2][1];
                ofu[m][1][2] = oa[m][3][0]; ofu[m][1][3] = oa[m][3][1];
#pragma unroll
                for (int j = 0; j < 4; j++) {
                    ofu[m][2][j] = exch[(pw * 16 + m * 8 + j) * 32 + lane];
                    ofu[m][3][j] = exch[(pw * 16 + m * 8 + 4 + j) * 32 + lane];
                }
            } else {
#pragma unroll
                for (int j = 0; j < 4; j++) {
                    ofu[m][0][j] = exch[(pw * 16 + m * 8 + j) * 32 + lane];
                    ofu[m][1][j] = exch[(pw * 16 + m * 8 + 4 + j) * 32 + lane];
                }
                ofu[m][2][0] = oa[m][0][0]; ofu[m][2][1] = oa[m][0][1];
                ofu[m][2][2] = oa[m][1][0]; ofu[m][2][3] = oa[m][1][1];
                ofu[m][3][0] = oa[m][2][0]; ofu[m][3][1] = oa[m][2][1];
                ofu[m][3][2] = oa[m][3][0]; ofu[m][3][3] = oa[m][3][1];
            }
        }

        // ---- phase D: H half = relu(O @ W24^T + b24), full K ----
#pragma unroll
        for (int m = 0; m < 2; m++)
#pragma unroll
        for (int ntp = 0; ntp < 4; ntp++) {
            const int ntg = 4 * hh + ntp;
            float dd[4] = {0.f, 0.f, 0.f, 0.f};
            const unsigned* wr = sW + 3 * 2048 + (ntg * 8 + gid) * 32;
#pragma unroll
            for (int kcg = 0; kcg < 4; kcg++) {
                unsigned b0, b1;
                ld_pair(wr + ((kcg ^ g3) << 3) + 2 * tig, b0, b1);
                mma16(dd, ofu[m][kcg], b0, b1);
            }
            const float2 bc = *(const float2*)(sBias + 192 + ntg * 8 + 2 * tig);
            ha[m][ntp][0] = ph2(fmaxf(dd[0] + bc.x, 0.f), fmaxf(dd[1] + bc.y, 0.f));
            ha[m][ntp][1] = ph2(fmaxf(dd[2] + bc.x, 0.f), fmaxf(dd[3] + bc.y, 0.f));
        }
        PAIRBAR();                 // WAR: partner done reading O exch

        // ---- exchange H halves ----
#pragma unroll
        for (int m = 0; m < 2; m++)
#pragma unroll
            for (int h = 0; h < 4; h++) {
                exch[(w * 16 + m * 8 + h * 2 + 0) * 32 + lane] = ha[m][h][0];
                exch[(w * 16 + m * 8 + h * 2 + 1) * 32 + lane] = ha[m][h][1];
            }
        PAIRBAR();
#pragma unroll
        for (int m = 0; m < 2; m++) {
            if (hh == 0) {
                ofu[m][0][0] = ha[m][0][0]; ofu[m][0][1] = ha[m][0][1];
                ofu[m][0][2] = ha[m][1][0]; ofu[m][0][3] = ha[m][1][1];
                ofu[m][1][0] = ha[m][2][0]; ofu[m][1][1] = ha[m][2][1];
                ofu[m][1][2] = ha[m][3][0]; ofu[m][1][3] = ha[m][3][1];
#pragma unroll
                for (int j = 0; j < 4; j++) {
                    ofu[m][2][j] = exch[(pw * 16 + m * 8 + j) * 32 + lane];
                    ofu[m][3][j] = exch[(pw * 16 + m * 8 + 4 + j) * 32 + lane];
                }
            } else {
#pragma unroll
                for (int j = 0; j < 4; j++) {
                    ofu[m][0][j] = exch[(pw * 16 + m * 8 + j) * 32 + lane];
                    ofu[m][1][j] = exch[(pw * 16 + m * 8 + 4 + j) * 32 + lane];
                }
                ofu[m][2][0] = ha[m][0][0]; ofu[m][2][1] = ha[m][0][1];
                ofu[m][2][2] = ha[m][1][0]; ofu[m][2][3] = ha[m][1][1];
                ofu[m][3][0] = ha[m][2][0]; ofu[m][3][1] = ha[m][2][1];
                ofu[m][3][2] = ha[m][3][0]; ofu[m][3][3] = ha[m][3][1];
            }
        }

        // ---- phase E: out half = H @ W25^T + b25 -> global ----
#pragma unroll
        for (int m = 0; m < 2; m++) {
            const int node = node0 + m;
            const bool vm = m ? v1 : v0;
            float* o0 = Out + ((size_t)(b * 12 + gid) * Nn + node) * 64;
            float* o1 = Out + ((size_t)(b * 12 + gid + 8) * Nn + node) * 64;
#pragma unroll
            for (int ntp = 0; ntp < 4; ntp++) {
                const int ntg = 4 * hh + ntp;
                float dd[4] = {0.f, 0.f, 0.f, 0.f};
                const unsigned* wr = sW + 4 * 2048 + (ntg * 8 + gid) * 32;
#pragma unroll
                for (int kcg = 0; kcg < 4; kcg++) {
                    unsigned b0, b1;
                    ld_pair(wr + ((kcg ^ g3) << 3) + 2 * tig, b0, b1);
                    mma16(dd, ofu[m][kcg], b0, b1);
                }
                const float2 bc = *(const float2*)(sBias + 256 + ntg * 8 + 2 * tig);
                const int c = ntg * 8 + 2 * tig;
                if (vm) {
                    *(float2*)(o0 + c) = make_float2(dd[0] + bc.x, dd[1] + bc.y);
                    if (gid < 4)
                        *(float2*)(o1 + c) = make_float2(dd[2] + bc.x, dd[3] + bc.y);
                }
            }
        }
        PAIRBAR();                 // WAR: partner done reading H exch

#pragma unroll
        for (int i = 0; i < 6; i++) gof[i] += 384;
    }
#undef PREFETCH
#undef STS_IN
#undef LOADF2
#undef GEMM_AB
#undef PAIRBAR
}

extern "C" void kernel_launch(void* const* d_in, const int* in_sizes, int n_in,
                              void* d_out, int out_size)
{
    const float* X     = (const float*)d_in[0];
    const float* STE_P = (const float*)d_in[1];
    const float* STE_Q = (const float*)d_in[2];
    const float* W21   = (const float*)d_in[3];
    const float* b21   = (const float*)d_in[4];
    const float* W22   = (const float*)d_in[5];
    const float* b22   = (const float*)d_in[6];
    const float* W23   = (const float*)d_in[7];
    const float* b23   = (const float*)d_in[8];
    const float* W24   = (const float*)d_in[9];
    const float* b24   = (const float*)d_in[10];
    const float* W25   = (const float*)d_in[11];
    const float* b25   = (const float*)d_in[12];
    float* Out = (float*)d_out;

    const size_t smem_bytes = (size_t)U_TOT * 4;          // 66,816 B -> 3 CTAs/SM

    cudaFuncSetAttribute(fused_pair_kernel,
                         cudaFuncAttributeMaxDynamicSharedMemorySize,
                         (int)smem_bytes);

    dim3 grid((Nn + NODES - 1) / NODES, Bsz);             // (167, 8)
    fused_pair_kernel<<<grid, THREADS, smem_bytes>>>(
        X, STE_P, STE_Q,
        W21, b21, W22, b22, W23, b23, W24, b24, W25, b25,
        Out);
}

// round 15
// speedup vs baseline: 1.6116x; 1.0679x over previous
#include <cuda_runtime.h>
#include <cstdint>

#define Bsz 8
#define Nn 5000
#define NG 6                 // node-groups per block
#define NODES (6 * NG)       // 36 nodes per block
#define THREADS 192          // 6 warps, one node per warp per group

// smem layout in 4B units
#define U_W    0             // 5 * 2048 (all five weights, fp16 frag layout)
#define U_BIAS 10240         // 320 f32
#define U_A    10560         // 96*32 fp16 frag slab (input staging only)
#define U_TOT  13632         // 54,528 B -> 4 CTAs/SM

typedef unsigned long long u64;

// ---------------- helpers ----------------
__device__ __forceinline__ unsigned ph2(float x, float y) {   // lo = x, hi = y
    unsigned r;
    asm("cvt.rn.f16x2.f32 %0, %1, %2;" : "=r"(r) : "f"(y), "f"(x));
    return r;
}
__device__ __forceinline__ void ld_pair(const unsigned* p, unsigned& lo, unsigned& hi) {
    const u64 v = *(const u64*)p;
    lo = (unsigned)v; hi = (unsigned)(v >> 32);
}
__device__ __forceinline__ int posj(int jj) { return ((jj & 3) << 1) | (jj >> 2); }

__device__ __forceinline__ void mma16(float d[4], const unsigned a[4],
                                      unsigned b0, unsigned b1) {
    asm volatile(
        "mma.sync.aligned.m16n8k16.row.col.f32.f16.f16.f32 "
        "{%0,%1,%2,%3}, {%4,%5,%6,%7}, {%8,%9}, {%0,%1,%2,%3};"
        : "+f"(d[0]), "+f"(d[1]), "+f"(d[2]), "+f"(d[3])
        : "r"(a[0]), "r"(a[1]), "r"(a[2]), "r"(a[3]), "r"(b0), "r"(b1));
}
__device__ __forceinline__ void mma8(float d[4], unsigned a0, unsigned a1, unsigned b0) {
    asm volatile(
        "mma.sync.aligned.m16n8k8.row.col.f32.f16.f16.f32 "
        "{%0,%1,%2,%3}, {%4,%5}, {%6}, {%0,%1,%2,%3};"
        : "+f"(d[0]), "+f"(d[1]), "+f"(d[2]), "+f"(d[3])
        : "r"(a0), "r"(a1), "r"(b0));
}

// ---------------- kernel ----------------
__global__ void __launch_bounds__(THREADS, 4)
fused_reg4_kernel(const float* __restrict__ X,
                  const float* __restrict__ STE_P,
                  const float* __restrict__ STE_Q,
                  const float* __restrict__ W21, const float* __restrict__ b21,
                  const float* __restrict__ W22, const float* __restrict__ b22,
                  const float* __restrict__ W23, const float* __restrict__ b23,
                  const float* __restrict__ W24, const float* __restrict__ b24,
                  const float* __restrict__ W25, const float* __restrict__ b25,
                  float* __restrict__ Out)
{
    extern __shared__ unsigned sm[];
    unsigned* sW = sm + U_W;
    float*    sBias = (float*)(sm + U_BIAS);
    unsigned* sA = sm + U_A;

    const int tid  = threadIdx.x;
    const int w    = tid >> 5;
    const int lane = tid & 31;
    const int gid  = lane >> 2;
    const int tig  = lane & 3;
    const int g3   = gid & 3;
    const int b    = blockIdx.y;
    const int n0   = blockIdx.x * NODES;

    const int r0 = 16 * w + gid;
    const int r1 = r0 + 8;

    // staging indices for group 0 (per group: node += 6 -> gof += 384)
    int gof[6], sap[6];
#pragma unroll
    for (int i = 0; i < 6; i++) {
        const int idx = lane + 32 * i;
        const int row = idx >> 4, c4 = idx & 15;
        gof[i] = ((b * 12 + row) * Nn + (n0 + w)) * 64 + c4 * 4;
        sap[i] = (16 * w + row) * 32 + (((c4 >> 2) ^ (row & 3)) << 3)
                 + posj((2 * c4) & 7);
    }

    if (tid < 64) {
        sBias[tid]       = b21[tid];
        sBias[64 + tid]  = b22[tid];
        sBias[128 + tid] = b23[tid];
        sBias[192 + tid] = b24[tid];
        sBias[256 + tid] = b25[tid];
    }

    // stage all five weights once (fp16 frag layout)
    {
        const float* Ws[5] = { W21, W22, W23, W24, W25 };
#pragma unroll
        for (int s = 0; s < 5; s++) {
            unsigned* dw = sW + s * 2048;
#pragma unroll
            for (int it = 0; it < 6; it++) {
                const int idx = tid + it * THREADS;
                if (idx < 1024) {
                    const int n = idx >> 4, c4 = idx & 15;
                    const float4 v = *(const float4*)(Ws[s] + n * 64 + c4 * 4);
                    const int a0 = n * 32 + (((c4 >> 2) ^ (n & 3)) << 3)
                                   + posj((2 * c4) & 7);
                    dw[a0]     = ph2(v.x, v.y);
                    dw[a0 + 2] = ph2(v.z, v.w);
                }
            }
        }
    }

    // zero pad rows 12-15 of this warp's slab (stay zero across all groups)
    ((uint4*)(sA + (16 * w + 12) * 32))[lane] = make_uint4(0, 0, 0, 0);

    uint2 hx[6];
    // stage group-0 STE_Q
    if (n0 + w < Nn) {
#pragma unroll
        for (int i = 0; i < 6; i++) {
            const float4 v = *(const float4*)(STE_Q + gof[i]);
            sA[sap[i]]     = ph2(v.x, v.y);
            sA[sap[i] + 2] = ph2(v.z, v.w);
        }
    }
    __syncthreads();                                     // the ONLY block sync

#define PREFETCH_AT(src, off)                                               \
    if (valid) {                                                            \
        _Pragma("unroll")                                                   \
        for (int i = 0; i < 6; i++) {                                       \
            const float4 v = *(const float4*)((src) + gof[i] + (off));      \
            hx[i].x = ph2(v.x, v.y);                                        \
            hx[i].y = ph2(v.z, v.w);                                        \
        }                                                                   \
    }

#define STS_IN()                                                            \
    {                                                                       \
        _Pragma("unroll")                                                   \
        for (int i = 0; i < 6; i++) {                                       \
            sA[sap[i]]     = hx[i].x;                                       \
            sA[sap[i] + 2] = hx[i].y;                                       \
        }                                                                   \
    }

#define LOAD_A(a)                                                           \
    {                                                                       \
        _Pragma("unroll")                                                   \
        for (int kc = 0; kc < 4; kc++) {                                    \
            const int off = ((kc ^ g3) << 3) + 2 * tig;                     \
            ld_pair(sA + r0 * 32 + off, (a)[kc][0], (a)[kc][2]);            \
            ld_pair(sA + r1 * 32 + off, (a)[kc][1], (a)[kc][3]);            \
        }                                                                   \
    }

#define GEMM_PACK(wsel, boff, mult, dst)                                    \
    {                                                                       \
        _Pragma("unroll")                                                   \
        for (int nt = 0; nt < 8; nt++) {                                    \
            float dd[4] = {0.f, 0.f, 0.f, 0.f};                             \
            const unsigned* wr = sW + (wsel) * 2048 + (nt * 8 + gid) * 32;  \
            _Pragma("unroll")                                               \
            for (int kc = 0; kc < 4; kc++) {                                \
                unsigned b0, b1;                                            \
                ld_pair(wr + ((kc ^ g3) << 3) + 2 * tig, b0, b1);           \
                mma16(dd, a[kc], b0, b1);                                   \
            }                                                               \
            const float2 bc = *(const float2*)(sBias + (boff) + nt * 8 + 2 * tig); \
            (dst)[nt][0] = ph2(fmaxf(dd[0] + bc.x, 0.f) * (mult),           \
                               fmaxf(dd[1] + bc.y, 0.f) * (mult));          \
            (dst)[nt][1] = ph2(fmaxf(dd[2] + bc.x, 0.f) * (mult),           \
                               fmaxf(dd[3] + bc.y, 0.f) * (mult));          \
        }                                                                   \
    }

#define GEMM_REG(wsel, src, nt, dd)                                         \
    {                                                                       \
        const unsigned* wr = sW + (wsel) * 2048 + ((nt) * 8 + gid) * 32;    \
        _Pragma("unroll")                                                   \
        for (int kc = 0; kc < 4; kc++) {                                    \
            unsigned aR[4] = { (src)[2 * kc][0], (src)[2 * kc][1],          \
                               (src)[2 * kc + 1][0], (src)[2 * kc + 1][1] };\
            unsigned b0, b1;                                                \
            ld_pair(wr + ((kc ^ g3) << 3) + 2 * tig, b0, b1);               \
            mma16(dd, aR, b0, b1);                                          \
        }                                                                   \
    }

    unsigned a[4][4];
    // register-dieted arrays: qo holds Q then O; kh holds K then H
    unsigned qo[8][2], kh[8][2], vb[8][2];
    const float scale = 0.35355339059327373f;            // 1/sqrt(8), folded into Q

#pragma unroll 1
    for (int g = 0; g < NG; g++) {
        const int node = n0 + g * 6 + w;
        const bool valid = (node < Nn);

        // ---- phase A: Q (scaled) -> qo regs ; stage STE_P ----
        PREFETCH_AT(STE_P, 0);
        LOAD_A(a);
        __syncwarp();
        STS_IN();
        GEMM_PACK(0, 0, scale, qo);
        __syncwarp();

        // ---- phase B: K -> kh regs ; stage X ----
        PREFETCH_AT(X, 0);
        LOAD_A(a);
        __syncwarp();
        STS_IN();
        GEMM_PACK(1, 64, 1.f, kh);
        __syncwarp();

        // ---- phase C (transposed): Vt = W23 * X^T -> vb regs ----
        // prefetch NEXT group's STE_Q during phase C MMAs
        {
            const bool validn = (node + 6 < Nn) && (g + 1 < NG);
#pragma unroll
            for (int i = 0; i < 6; i++) {
                if (validn) {
                    const float4 v = *(const float4*)(STE_Q + gof[i] + 384);
                    hx[i].x = ph2(v.x, v.y);
                    hx[i].y = ph2(v.z, v.w);
                }
            }
        }
#pragma unroll
        for (int mt = 0; mt < 4; mt++) {
            unsigned wa[4][4];
#pragma unroll
            for (int kc = 0; kc < 4; kc++) {
                const int off = ((kc ^ g3) << 3) + 2 * tig;
                ld_pair(sW + 2 * 2048 + (16 * mt + gid) * 32 + off, wa[kc][0], wa[kc][2]);
                ld_pair(sW + 2 * 2048 + (16 * mt + 8 + gid) * 32 + off, wa[kc][1], wa[kc][3]);
            }
            const float bj0 = sBias[128 + 16 * mt + gid];
            const float bj1 = sBias[128 + 16 * mt + 8 + gid];
            float d0[4] = {0.f, 0.f, 0.f, 0.f};
            float d1[4] = {0.f, 0.f, 0.f, 0.f};
#pragma unroll
            for (int kc = 0; kc < 4; kc++) {
                const int off = ((kc ^ g3) << 3) + 2 * tig;
                unsigned b0, b1;
                ld_pair(sA + r0 * 32 + off, b0, b1);
                mma16(d0, wa[kc], b0, b1);
                ld_pair(sA + r1 * 32 + off, b0, b1);
                mma16(d1, wa[kc], b0, b1);
            }
            vb[2 * mt][0]     = ph2(fmaxf(d0[0] + bj0, 0.f), fmaxf(d0[1] + bj0, 0.f));
            vb[2 * mt][1]     = ph2(fmaxf(d1[0] + bj0, 0.f), fmaxf(d1[1] + bj0, 0.f));
            vb[2 * mt + 1][0] = ph2(fmaxf(d0[2] + bj1, 0.f), fmaxf(d0[3] + bj1, 0.f));
            vb[2 * mt + 1][1] = ph2(fmaxf(d1[2] + bj1, 0.f), fmaxf(d1[3] + bj1, 0.f));
        }
        __syncwarp();                                    // slab reads done
        // stage next group's STE_Q (warp-local rows)
        if ((node + 6 < Nn) && (g + 1 < NG)) { STS_IN(); }
        __syncwarp();

        // ---- attention: per head, in registers; O overwrites Q (qo) ----
#pragma unroll
        for (int h = 0; h < 8; h++) {
            float s1[4] = {0.f, 0.f, 0.f, 0.f};
            float s2[4] = {0.f, 0.f, 0.f, 0.f};
            mma8(s1, qo[h][0], qo[h][1], kh[h][0]);      // p = 0..7
            mma8(s2, qo[h][0], qo[h][1], kh[h][1]);      // p = 8..15 (12-15 masked)
            const float e10 = __expf(s1[0] - 8.f), e11 = __expf(s1[1] - 8.f);
            const float e12 = __expf(s1[2] - 8.f), e13 = __expf(s1[3] - 8.f);
            float e20 = 0.f, e21 = 0.f, e22 = 0.f, e23 = 0.f;
            if (tig < 2) {                               // p = 8+2tig < 12
                e20 = __expf(s2[0] - 8.f); e21 = __expf(s2[1] - 8.f);
                e22 = __expf(s2[2] - 8.f); e23 = __expf(s2[3] - 8.f);
            }
            float sumA = e10 + e11 + e20 + e21;
            float sumB = e12 + e13 + e22 + e23;
            sumA += __shfl_xor_sync(0xffffffffu, sumA, 1);
            sumA += __shfl_xor_sync(0xffffffffu, sumA, 2);
            sumB += __shfl_xor_sync(0xffffffffu, sumB, 1);
            sumB += __shfl_xor_sync(0xffffffffu, sumB, 2);
            const float invA = __fdividef(1.f, sumA);
            const float invB = __fdividef(1.f, sumB);
            unsigned pa[4];
            pa[0] = ph2(e10 * invA, e11 * invA);
            pa[1] = ph2(e12 * invB, e13 * invB);
            pa[2] = ph2(e20 * invA, e21 * invA);
            pa[3] = ph2(e22 * invB, e23 * invB);
            float ov[4] = {0.f, 0.f, 0.f, 0.f};
            mma16(ov, pa, vb[h][0], vb[h][1]);
            qo[h][0] = ph2(ov[0], ov[1]);                // O over Q
            qo[h][1] = ph2(ov[2], ov[3]);
        }

        // ---- phase D: H = relu(O @ W24^T + b24) -> kh (over K) ----
#pragma unroll
        for (int nt = 0; nt < 8; nt++) {
            float dd[4] = {0.f, 0.f, 0.f, 0.f};
            GEMM_REG(3, qo, nt, dd);
            const float2 bc = *(const float2*)(sBias + 192 + nt * 8 + 2 * tig);
            kh[nt][0] = ph2(fmaxf(dd[0] + bc.x, 0.f), fmaxf(dd[1] + bc.y, 0.f));
            kh[nt][1] = ph2(fmaxf(dd[2] + bc.x, 0.f), fmaxf(dd[3] + bc.y, 0.f));
        }

        // ---- phase E: out = H @ W25^T + b25 -> global ----
        {
            float* o0 = Out + ((size_t)(b * 12 + gid) * Nn + node) * 64;
            float* o1 = Out + ((size_t)(b * 12 + gid + 8) * Nn + node) * 64;
#pragma unroll
            for (int nt = 0; nt < 8; nt++) {
                float dd[4] = {0.f, 0.f, 0.f, 0.f};
                GEMM_REG(4, kh, nt, dd);
                const float2 bc = *(const float2*)(sBias + 256 + nt * 8 + 2 * tig);
                if (valid) {
                    *(float2*)(o0 + nt * 8 + 2 * tig) =
                        make_float2(dd[0] + bc.x, dd[1] + bc.y);
                    if (gid < 4)
                        *(float2*)(o1 + nt * 8 + 2 * tig) =
                            make_float2(dd[2] + bc.x, dd[3] + bc.y);
                }
            }
        }

        // advance to next group (node += 6 -> +384 floats)
#pragma unroll
        for (int i = 0; i < 6; i++) gof[i] += 384;
    }
#undef PREFETCH_AT
#undef STS_IN
#undef LOAD_A
#undef GEMM_PACK
#undef GEMM_REG
}

extern "C" void kernel_launch(void* const* d_in, const int* in_sizes, int n_in,
                              void* d_out, int out_size)
{
    const float* X     = (const float*)d_in[0];
    const float* STE_P = (const float*)d_in[1];
    const float* STE_Q = (const float*)d_in[2];
    const float* W21   = (const float*)d_in[3];
    const float* b21   = (const float*)d_in[4];
    const float* W22   = (const float*)d_in[5];
    const float* b22   = (const float*)d_in[6];
    const float* W23   = (const float*)d_in[7];
    const float* b23   = (const float*)d_in[8];
    const float* W24   = (const float*)d_in[9];
    const float* b24   = (const float*)d_in[10];
    const float* W25   = (const float*)d_in[11];
    const float* b25   = (const float*)d_in[12];
    float* Out = (float*)d_out;

    const size_t smem_bytes = (size_t)U_TOT * 4;          // 54,528 B -> 4 CTAs/SM

    cudaFuncSetAttribute(fused_reg4_kernel,
                         cudaFuncAttributeMaxDynamicSharedMemorySize,
                         (int)smem_bytes);

    dim3 grid((Nn + NODES - 1) / NODES, Bsz);             // (139, 8) = 1112 CTAs
    fused_reg4_kernel<<<grid, THREADS, smem_bytes>>>(
        X, STE_P, STE_Q,
        W21, b21, W22, b22, W23, b23, W24, b24, W25, b25,
        Out);
}

// round 16
// speedup vs baseline: 1.8762x; 1.1642x over previous
#include <cuda_runtime.h>
#include <cstdint>

#define Bsz 8
#define Nn 5000
#define NG 5                 // node-groups per block
#define NODES (6 * NG)       // 30 nodes per block
#define THREADS 192          // 6 warps, one node per warp per group

// smem layout in 4B units
#define U_W    0             // 5 * 2048 (all five weights, fp16 frag layout)
#define U_BIAS 10240         // 320 f32
#define U_A    10560         // 96*32 fp16 frag slab (input staging only)
#define U_TOT  13632         // 54,528 B -> 3 CTAs/SM

typedef unsigned long long u64;

// ---------------- helpers ----------------
__device__ __forceinline__ unsigned ph2(float x, float y) {   // lo = x, hi = y
    unsigned r;
    asm("cvt.rn.f16x2.f32 %0, %1, %2;" : "=r"(r) : "f"(y), "f"(x));
    return r;
}
__device__ __forceinline__ void ld_pair(const unsigned* p, unsigned& lo, unsigned& hi) {
    const u64 v = *(const u64*)p;
    lo = (unsigned)v; hi = (unsigned)(v >> 32);
}
__device__ __forceinline__ int posj(int jj) { return ((jj & 3) << 1) | (jj >> 2); }

__device__ __forceinline__ void mma16(float d[4], const unsigned a[4],
                                      unsigned b0, unsigned b1) {
    asm volatile(
        "mma.sync.aligned.m16n8k16.row.col.f32.f16.f16.f32 "
        "{%0,%1,%2,%3}, {%4,%5,%6,%7}, {%8,%9}, {%0,%1,%2,%3};"
        : "+f"(d[0]), "+f"(d[1]), "+f"(d[2]), "+f"(d[3])
        : "r"(a[0]), "r"(a[1]), "r"(a[2]), "r"(a[3]), "r"(b0), "r"(b1));
}
__device__ __forceinline__ void mma8(float d[4], unsigned a0, unsigned a1, unsigned b0) {
    asm volatile(
        "mma.sync.aligned.m16n8k8.row.col.f32.f16.f16.f32 "
        "{%0,%1,%2,%3}, {%4,%5}, {%6}, {%0,%1,%2,%3};"
        : "+f"(d[0]), "+f"(d[1]), "+f"(d[2]), "+f"(d[3])
        : "r"(a0), "r"(a1), "r"(b0));
}

// ---------------- kernel ----------------
__global__ void __launch_bounds__(THREADS, 3)
fused_reg_kernel(const float* __restrict__ X,
                 const float* __restrict__ STE_P,
                 const float* __restrict__ STE_Q,
                 const float* __restrict__ W21, const float* __restrict__ b21,
                 const float* __restrict__ W22, const float* __restrict__ b22,
                 const float* __restrict__ W23, const float* __restrict__ b23,
                 const float* __restrict__ W24, const float* __restrict__ b24,
                 const float* __restrict__ W25, const float* __restrict__ b25,
                 float* __restrict__ Out)
{
    extern __shared__ unsigned sm[];
    unsigned* sW = sm + U_W;
    float*    sBias = (float*)(sm + U_BIAS);
    unsigned* sA = sm + U_A;

    const int tid  = threadIdx.x;
    const int w    = tid >> 5;
    const int lane = tid & 31;
    const int gid  = lane >> 2;
    const int tig  = lane & 3;
    const int g3   = gid & 3;
    const int b    = blockIdx.y;
    const int n0   = blockIdx.x * NODES;

    const int r0 = 16 * w + gid;
    const int r1 = r0 + 8;

    // staging indices for group 0 (per group: node += 6 -> gof += 384)
    int gof[6], sap[6];
#pragma unroll
    for (int i = 0; i < 6; i++) {
        const int idx = lane + 32 * i;
        const int row = idx >> 4, c4 = idx & 15;
        gof[i] = ((b * 12 + row) * Nn + (n0 + w)) * 64 + c4 * 4;
        sap[i] = (16 * w + row) * 32 + (((c4 >> 2) ^ (row & 3)) << 3)
                 + posj((2 * c4) & 7);
    }

    if (tid < 64) {
        sBias[tid]       = b21[tid];
        sBias[64 + tid]  = b22[tid];
        sBias[128 + tid] = b23[tid];
        sBias[192 + tid] = b24[tid];
        sBias[256 + tid] = b25[tid];
    }

    // stage all five weights once (fp16 frag layout)
    {
        const float* Ws[5] = { W21, W22, W23, W24, W25 };
#pragma unroll
        for (int s = 0; s < 5; s++) {
            unsigned* dw = sW + s * 2048;
#pragma unroll
            for (int it = 0; it < 6; it++) {
                const int idx = tid + it * THREADS;
                if (idx < 1024) {
                    const int n = idx >> 4, c4 = idx & 15;
                    const float4 v = *(const float4*)(Ws[s] + n * 64 + c4 * 4);
                    const int a0 = n * 32 + (((c4 >> 2) ^ (n & 3)) << 3)
                                   + posj((2 * c4) & 7);
                    dw[a0]     = ph2(v.x, v.y);
                    dw[a0 + 2] = ph2(v.z, v.w);
                }
            }
        }
    }

    // zero pad rows 12-15 of this warp's slab (stay zero across all groups)
    ((uint4*)(sA + (16 * w + 12) * 32))[lane] = make_uint4(0, 0, 0, 0);

    uint2 hx[6];
    // stage group-0 STE_Q
    if (n0 + w < Nn) {
#pragma unroll
        for (int i = 0; i < 6; i++) {
            const float4 v = *(const float4*)(STE_Q + gof[i]);
            sA[sap[i]]     = ph2(v.x, v.y);
            sA[sap[i] + 2] = ph2(v.z, v.w);
        }
    }
    __syncthreads();                                     // the ONLY block sync

#define PREFETCH_AT(src, off)                                               \
    if (valid) {                                                            \
        _Pragma("unroll")                                                   \
        for (int i = 0; i < 6; i++) {                                       \
            const float4 v = *(const float4*)((src) + gof[i] + (off));      \
            hx[i].x = ph2(v.x, v.y);                                        \
            hx[i].y = ph2(v.z, v.w);                                        \
        }                                                                   \
    }

#define STS_IN()                                                            \
    {                                                                       \
        _Pragma("unroll")                                                   \
        for (int i = 0; i < 6; i++) {                                       \
            sA[sap[i]]     = hx[i].x;                                       \
            sA[sap[i] + 2] = hx[i].y;                                       \
        }                                                                   \
    }

#define LOAD_A(a)                                                           \
    {                                                                       \
        _Pragma("unroll")                                                   \
        for (int kc = 0; kc < 4; kc++) {                                    \
            const int off = ((kc ^ g3) << 3) + 2 * tig;                     \
            ld_pair(sA + r0 * 32 + off, (a)[kc][0], (a)[kc][2]);            \
            ld_pair(sA + r1 * 32 + off, (a)[kc][1], (a)[kc][3]);            \
        }                                                                   \
    }

#define GEMM_PACK(wsel, boff, mult, dst)                                    \
    {                                                                       \
        _Pragma("unroll")                                                   \
        for (int nt = 0; nt < 8; nt++) {                                    \
            float dd[4] = {0.f, 0.f, 0.f, 0.f};                             \
            const unsigned* wr = sW + (wsel) * 2048 + (nt * 8 + gid) * 32;  \
            _Pragma("unroll")                                               \
            for (int kc = 0; kc < 4; kc++) {                                \
                unsigned b0, b1;                                            \
                ld_pair(wr + ((kc ^ g3) << 3) + 2 * tig, b0, b1);           \
                mma16(dd, a[kc], b0, b1);                                   \
            }                                                               \
            const float2 bc = *(const float2*)(sBias + (boff) + nt * 8 + 2 * tig); \
            (dst)[nt][0] = ph2(fmaxf(dd[0] + bc.x, 0.f) * (mult),           \
                               fmaxf(dd[1] + bc.y, 0.f) * (mult));          \
            (dst)[nt][1] = ph2(fmaxf(dd[2] + bc.x, 0.f) * (mult),           \
                               fmaxf(dd[3] + bc.y, 0.f) * (mult));          \
        }                                                                   \
    }

#define GEMM_REG(wsel, src, nt, dd)                                         \
    {                                                                       \
        const unsigned* wr = sW + (wsel) * 2048 + ((nt) * 8 + gid) * 32;    \
        _Pragma("unroll")                                                   \
        for (int kc = 0; kc < 4; kc++) {                                    \
            unsigned aR[4] = { (src)[2 * kc][0], (src)[2 * kc][1],          \
                               (src)[2 * kc + 1][0], (src)[2 * kc + 1][1] };\
            unsigned b0, b1;                                                \
            ld_pair(wr + ((kc ^ g3) << 3) + 2 * tig, b0, b1);               \
            mma16(dd, aR, b0, b1);                                          \
        }                                                                   \
    }

    unsigned a[4][4];
    unsigned qa[8][2], kb[8][2], vb[8][2], oa[8][2], ha[8][2];
    const float scale = 0.35355339059327373f;            // 1/sqrt(8), folded into Q

#pragma unroll 1
    for (int g = 0; g < NG; g++) {
        const int node = n0 + g * 6 + w;
        const bool valid = (node < Nn);

        // ---- phase A: prefetch STE_P ; GEMM Q from slab ; then STS P ----
        PREFETCH_AT(STE_P, 0);          // LDG issues here...
        LOAD_A(a);                      // Q frags from slab
        GEMM_PACK(0, 0, scale, qa);     // ...and completes under these 32 MMAs
        STS_IN();                       // P -> slab (own rows)
        __syncwarp();                   // cross-lane visibility for next LOAD_A

        // ---- phase B: prefetch X ; GEMM K from slab ; then STS X ----
        PREFETCH_AT(X, 0);
        LOAD_A(a);                      // P frags
        GEMM_PACK(1, 64, 1.f, kb);
        STS_IN();                       // X -> slab
        __syncwarp();

        // ---- phase C (transposed): Vt = W23 * X^T -> vb regs ----
        // prefetch NEXT group's STE_Q during phase C MMAs
        {
            const bool validn = (node + 6 < Nn) && (g + 1 < NG);
#pragma unroll
            for (int i = 0; i < 6; i++) {
                if (validn) {
                    const float4 v = *(const float4*)(STE_Q + gof[i] + 384);
                    hx[i].x = ph2(v.x, v.y);
                    hx[i].y = ph2(v.z, v.w);
                }
            }
        }
#pragma unroll
        for (int mt = 0; mt < 4; mt++) {
            unsigned wa[4][4];
#pragma unroll
            for (int kc = 0; kc < 4; kc++) {
                const int off = ((kc ^ g3) << 3) + 2 * tig;
                ld_pair(sW + 2 * 2048 + (16 * mt + gid) * 32 + off, wa[kc][0], wa[kc][2]);
                ld_pair(sW + 2 * 2048 + (16 * mt + 8 + gid) * 32 + off, wa[kc][1], wa[kc][3]);
            }
            const float bj0 = sBias[128 + 16 * mt + gid];
            const float bj1 = sBias[128 + 16 * mt + 8 + gid];
            float d0[4] = {0.f, 0.f, 0.f, 0.f};
            float d1[4] = {0.f, 0.f, 0.f, 0.f};
#pragma unroll
            for (int kc = 0; kc < 4; kc++) {
                const int off = ((kc ^ g3) << 3) + 2 * tig;
                unsigned b0, b1;
                ld_pair(sA + r0 * 32 + off, b0, b1);
                mma16(d0, wa[kc], b0, b1);
                ld_pair(sA + r1 * 32 + off, b0, b1);
                mma16(d1, wa[kc], b0, b1);
            }
            vb[2 * mt][0]     = ph2(fmaxf(d0[0] + bj0, 0.f), fmaxf(d0[1] + bj0, 0.f));
            vb[2 * mt][1]     = ph2(fmaxf(d1[0] + bj0, 0.f), fmaxf(d1[1] + bj0, 0.f));
            vb[2 * mt + 1][0] = ph2(fmaxf(d0[2] + bj1, 0.f), fmaxf(d0[3] + bj1, 0.f));
            vb[2 * mt + 1][1] = ph2(fmaxf(d1[2] + bj1, 0.f), fmaxf(d1[3] + bj1, 0.f));
        }
        __syncwarp();                                    // slab reads done
        // stage next group's STE_Q (warp-local rows)
        if ((node + 6 < Nn) && (g + 1 < NG)) { STS_IN(); }
        __syncwarp();

        // ---- attention: per head, all in registers ----
#pragma unroll
        for (int h = 0; h < 8; h++) {
            float s1[4] = {0.f, 0.f, 0.f, 0.f};
            float s2[4] = {0.f, 0.f, 0.f, 0.f};
            mma8(s1, qa[h][0], qa[h][1], kb[h][0]);      // p = 0..7
            mma8(s2, qa[h][0], qa[h][1], kb[h][1]);      // p = 8..15 (12-15 masked)
            const float e10 = __expf(s1[0] - 8.f), e11 = __expf(s1[1] - 8.f);
            const float e12 = __expf(s1[2] - 8.f), e13 = __expf(s1[3] - 8.f);
            float e20 = 0.f, e21 = 0.f, e22 = 0.f, e23 = 0.f;
            if (tig < 2) {                               // p = 8+2tig < 12
                e20 = __expf(s2[0] - 8.f); e21 = __expf(s2[1] - 8.f);
                e22 = __expf(s2[2] - 8.f); e23 = __expf(s2[3] - 8.f);
            }
            float sumA = e10 + e11 + e20 + e21;
            float sumB = e12 + e13 + e22 + e23;
            sumA += __shfl_xor_sync(0xffffffffu, sumA, 1);
            sumA += __shfl_xor_sync(0xffffffffu, sumA, 2);
            sumB += __shfl_xor_sync(0xffffffffu, sumB, 1);
            sumB += __shfl_xor_sync(0xffffffffu, sumB, 2);
            const float invA = __fdividef(1.f, sumA);
            const float invB = __fdividef(1.f, sumB);
            unsigned pa[4];
            pa[0] = ph2(e10 * invA, e11 * invA);
            pa[1] = ph2(e12 * invB, e13 * invB);
            pa[2] = ph2(e20 * invA, e21 * invA);
            pa[3] = ph2(e22 * invB, e23 * invB);
            float ov[4] = {0.f, 0.f, 0.f, 0.f};
            mma16(ov, pa, vb[h][0], vb[h][1]);
            oa[h][0] = ph2(ov[0], ov[1]);
            oa[h][1] = ph2(ov[2], ov[3]);
        }

        // ---- phase D: H = relu(attn @ W24^T + b24) -> ha regs ----
#pragma unroll
        for (int nt = 0; nt < 8; nt++) {
            float dd[4] = {0.f, 0.f, 0.f, 0.f};
            GEMM_REG(3, oa, nt, dd);
            const float2 bc = *(const float2*)(sBias + 192 + nt * 8 + 2 * tig);
            ha[nt][0] = ph2(fmaxf(dd[0] + bc.x, 0.f), fmaxf(dd[1] + bc.y, 0.f));
            ha[nt][1] = ph2(fmaxf(dd[2] + bc.x, 0.f), fmaxf(dd[3] + bc.y, 0.f));
        }

        // ---- phase E: out = H @ W25^T + b25 -> global ----
        {
            float* o0 = Out + ((size_t)(b * 12 + gid) * Nn + node) * 64;
            float* o1 = Out + ((size_t)(b * 12 + gid + 8) * Nn + node) * 64;
#pragma unroll
            for (int nt = 0; nt < 8; nt++) {
                float dd[4] = {0.f, 0.f, 0.f, 0.f};
                GEMM_REG(4, ha, nt, dd);
                const float2 bc = *(const float2*)(sBias + 256 + nt * 8 + 2 * tig);
                if (valid) {
                    *(float2*)(o0 + nt * 8 + 2 * tig) =
                        make_float2(dd[0] + bc.x, dd[1] + bc.y);
                    if (gid < 4)
                        *(float2*)(o1 + nt * 8 + 2 * tig) =
                            make_float2(dd[2] + bc.x, dd[3] + bc.y);
                }
            }
        }

        // advance to next group (node += 6 -> +384 floats)
#pragma unroll
        for (int i = 0; i < 6; i++) gof[i] += 384;
    }
#undef PREFETCH_AT
#undef STS_IN
#undef LOAD_A
#undef GEMM_PACK
#undef GEMM_REG
}

extern "C" void kernel_launch(void* const* d_in, const int* in_sizes, int n_in,
                              void* d_out, int out_size)
{
    const float* X     = (const float*)d_in[0];
    const float* STE_P = (const float*)d_in[1];
    const float* STE_Q = (const float*)d_in[2];
    const float* W21   = (const float*)d_in[3];
    const float* b21   = (const float*)d_in[4];
    const float* W22   = (const float*)d_in[5];
    const float* b22   = (const float*)d_in[6];
    const float* W23   = (const float*)d_in[7];
    const float* b23   = (const float*)d_in[8];
    const float* W24   = (const float*)d_in[9];
    const float* b24   = (const float*)d_in[10];
    const float* W25   = (const float*)d_in[11];
    const float* b25   = (const float*)d_in[12];
    float* Out = (float*)d_out;

    const size_t smem_bytes = (size_t)U_TOT * 4;          // 54,528 B -> 3 CTAs/SM

    cudaFuncSetAttribute(fused_reg_kernel,
                         cudaFuncAttributeMaxDynamicSharedMemorySize,
                         (int)smem_bytes);

    dim3 grid((Nn + NODES - 1) / NODES, Bsz);             // (167, 8) = 1336 CTAs
    fused_reg_kernel<<<grid, THREADS, smem_bytes>>>(
        X, STE_P, STE_Q,
        W21, b21, W22, b22, W23, b23, W24, b24, W25, b25,
        Out);
}

// round 17
// speedup vs baseline: 1.8934x; 1.0092x over previous
#include <cuda_runtime.h>
#include <cstdint>

#define Bsz 8
#define Nn 5000
#define NG 5                 // node-groups per block
#define NODES (6 * NG)       // 30 nodes per block
#define THREADS 192          // 6 warps, one node per warp per group

// smem layout in 4B units
#define U_W    0             // 5 * 2048 (all five weights, fp16 frag layout)
#define U_BIAS 10240         // 320 f32
#define U_A    10560         // 96*32 fp16 frag slab (input staging only)
#define U_TOT  13632         // 54,528 B -> 3 CTAs/SM

typedef unsigned long long u64;

// ---------------- helpers ----------------
__device__ __forceinline__ unsigned ph2(float x, float y) {   // lo = x, hi = y
    unsigned r;
    asm("cvt.rn.f16x2.f32 %0, %1, %2;" : "=r"(r) : "f"(y), "f"(x));
    return r;
}
__device__ __forceinline__ void ld_pair(const unsigned* p, unsigned& lo, unsigned& hi) {
    const u64 v = *(const u64*)p;
    lo = (unsigned)v; hi = (unsigned)(v >> 32);
}
__device__ __forceinline__ int posj(int jj) { return ((jj & 3) << 1) | (jj >> 2); }

__device__ __forceinline__ void mma16(float d[4], const unsigned a[4],
                                      unsigned b0, unsigned b1) {
    asm volatile(
        "mma.sync.aligned.m16n8k16.row.col.f32.f16.f16.f32 "
        "{%0,%1,%2,%3}, {%4,%5,%6,%7}, {%8,%9}, {%0,%1,%2,%3};"
        : "+f"(d[0]), "+f"(d[1]), "+f"(d[2]), "+f"(d[3])
        : "r"(a[0]), "r"(a[1]), "r"(a[2]), "r"(a[3]), "r"(b0), "r"(b1));
}
__device__ __forceinline__ void mma8(float d[4], unsigned a0, unsigned a1, unsigned b0) {
    asm volatile(
        "mma.sync.aligned.m16n8k8.row.col.f32.f16.f16.f32 "
        "{%0,%1,%2,%3}, {%4,%5}, {%6}, {%0,%1,%2,%3};"
        : "+f"(d[0]), "+f"(d[1]), "+f"(d[2]), "+f"(d[3])
        : "r"(a0), "r"(a1), "r"(b0));
}

// ---------------- kernel ----------------
__global__ void __launch_bounds__(THREADS, 3)
fused_reg_kernel(const float* __restrict__ X,
                 const float* __restrict__ STE_P,
                 const float* __restrict__ STE_Q,
                 const float* __restrict__ W21, const float* __restrict__ b21,
                 const float* __restrict__ W22, const float* __restrict__ b22,
                 const float* __restrict__ W23, const float* __restrict__ b23,
                 const float* __restrict__ W24, const float* __restrict__ b24,
                 const float* __restrict__ W25, const float* __restrict__ b25,
                 float* __restrict__ Out)
{
    extern __shared__ unsigned sm[];
    unsigned* sW = sm + U_W;
    float*    sBias = (float*)(sm + U_BIAS);
    unsigned* sA = sm + U_A;

    const int tid  = threadIdx.x;
    const int w    = tid >> 5;
    const int lane = tid & 31;
    const int gid  = lane >> 2;
    const int tig  = lane & 3;
    const int g3   = gid & 3;
    const int b    = blockIdx.y;
    const int n0   = blockIdx.x * NODES;

    const int r0 = 16 * w + gid;
    const int r1 = r0 + 8;

    // staging indices for group 0 (per group: node += 6 -> gof += 384)
    int gof[6], sap[6];
#pragma unroll
    for (int i = 0; i < 6; i++) {
        const int idx = lane + 32 * i;
        const int row = idx >> 4, c4 = idx & 15;
        gof[i] = ((b * 12 + row) * Nn + (n0 + w)) * 64 + c4 * 4;
        sap[i] = (16 * w + row) * 32 + (((c4 >> 2) ^ (row & 3)) << 3)
                 + posj((2 * c4) & 7);
    }

    if (tid < 64) {
        sBias[tid]       = b21[tid];
        sBias[64 + tid]  = b22[tid];
        sBias[128 + tid] = b23[tid];
        sBias[192 + tid] = b24[tid];
        sBias[256 + tid] = b25[tid];
    }

    // stage all five weights once (fp16 frag layout)
    {
        const float* Ws[5] = { W21, W22, W23, W24, W25 };
#pragma unroll
        for (int s = 0; s < 5; s++) {
            unsigned* dw = sW + s * 2048;
#pragma unroll
            for (int it = 0; it < 6; it++) {
                const int idx = tid + it * THREADS;
                if (idx < 1024) {
                    const int n = idx >> 4, c4 = idx & 15;
                    const float4 v = *(const float4*)(Ws[s] + n * 64 + c4 * 4);
                    const int a0 = n * 32 + (((c4 >> 2) ^ (n & 3)) << 3)
                                   + posj((2 * c4) & 7);
                    dw[a0]     = ph2(v.x, v.y);
                    dw[a0 + 2] = ph2(v.z, v.w);
                }
            }
        }
    }

    // zero pad rows 12-15 of this warp's slab (stay zero across all groups)
    ((uint4*)(sA + (16 * w + 12) * 32))[lane] = make_uint4(0, 0, 0, 0);

    uint2 hx[6];
    // stage group-0 STE_Q
    if (n0 + w < Nn) {
#pragma unroll
        for (int i = 0; i < 6; i++) {
            const float4 v = *(const float4*)(STE_Q + gof[i]);
            sA[sap[i]]     = ph2(v.x, v.y);
            sA[sap[i] + 2] = ph2(v.z, v.w);
        }
    }
    __syncthreads();                                     // the ONLY block sync

#define PREFETCH_AT(src, off)                                               \
    if (valid) {                                                            \
        _Pragma("unroll")                                                   \
        for (int i = 0; i < 6; i++) {                                       \
            const float4 v = *(const float4*)((src) + gof[i] + (off));      \
            hx[i].x = ph2(v.x, v.y);                                        \
            hx[i].y = ph2(v.z, v.w);                                        \
        }                                                                   \
    }

#define STS_IN()                                                            \
    {                                                                       \
        _Pragma("unroll")                                                   \
        for (int i = 0; i < 6; i++) {                                       \
            sA[sap[i]]     = hx[i].x;                                       \
            sA[sap[i] + 2] = hx[i].y;                                       \
        }                                                                   \
    }

#define LOAD_A(a)                                                           \
    {                                                                       \
        _Pragma("unroll")                                                   \
        for (int kc = 0; kc < 4; kc++) {                                    \
            const int off = ((kc ^ g3) << 3) + 2 * tig;                     \
            ld_pair(sA + r0 * 32 + off, (a)[kc][0], (a)[kc][2]);            \
            ld_pair(sA + r1 * 32 + off, (a)[kc][1], (a)[kc][3]);            \
        }                                                                   \
    }

#define GEMM_PACK(wsel, boff, mult, dst)                                    \
    {                                                                       \
        _Pragma("unroll")                                                   \
        for (int nt = 0; nt < 8; nt++) {                                    \
            float dd[4] = {0.f, 0.f, 0.f, 0.f};                             \
            const unsigned* wr = sW + (wsel) * 2048 + (nt * 8 + gid) * 32;  \
            _Pragma("unroll")                                               \
            for (int kc = 0; kc < 4; kc++) {                                \
                unsigned b0, b1;                                            \
                ld_pair(wr + ((kc ^ g3) << 3) + 2 * tig, b0, b1);           \
                mma16(dd, a[kc], b0, b1);                                   \
            }                                                               \
            const float2 bc = *(const float2*)(sBias + (boff) + nt * 8 + 2 * tig); \
            (dst)[nt][0] = ph2(fmaxf(dd[0] + bc.x, 0.f) * (mult),           \
                               fmaxf(dd[1] + bc.y, 0.f) * (mult));          \
            (dst)[nt][1] = ph2(fmaxf(dd[2] + bc.x, 0.f) * (mult),           \
                               fmaxf(dd[3] + bc.y, 0.f) * (mult));          \
        }                                                                   \
    }

#define GEMM_REG(wsel, src, nt, dd)                                         \
    {                                                                       \
        const unsigned* wr = sW + (wsel) * 2048 + ((nt) * 8 + gid) * 32;    \
        _Pragma("unroll")                                                   \
        for (int kc = 0; kc < 4; kc++) {                                    \
            unsigned aR[4] = { (src)[2 * kc][0], (src)[2 * kc][1],          \
                               (src)[2 * kc + 1][0], (src)[2 * kc + 1][1] };\
            unsigned b0, b1;                                                \
            ld_pair(wr + ((kc ^ g3) << 3) + 2 * tig, b0, b1);               \
            mma16(dd, aR, b0, b1);                                          \
        }                                                                   \
    }

    unsigned a[4][4];
    unsigned qa[8][2], kb[8][2], vb[8][2], oa[8][2], ha[8][2];
    const float scale = 0.35355339059327373f;            // 1/sqrt(8), folded into Q

#pragma unroll 1
    for (int g = 0; g < NG; g++) {
        const int node = n0 + g * 6 + w;
        const bool valid = (node < Nn);

        // ---- phase A: prefetch STE_P ; GEMM Q from slab ; then STS P ----
        PREFETCH_AT(STE_P, 0);          // LDG issues here...
        LOAD_A(a);                      // Q frags from slab
        GEMM_PACK(0, 0, scale, qa);     // ...and completes under these 32 MMAs
        STS_IN();                       // P -> slab (own rows)
        __syncwarp();                   // cross-lane visibility for next LOAD_A

        // ---- phase B: prefetch X ; GEMM K from slab ; then STS X ----
        PREFETCH_AT(X, 0);
        LOAD_A(a);                      // P frags
        GEMM_PACK(1, 64, 1.f, kb);
        STS_IN();                       // X -> slab
        __syncwarp();

        // ---- phase C (transposed): Vt = W23 * X^T -> vb regs ----
        // X slab frags loaded ONCE into regs; reused as B-operand for all 4 mt
        LOAD_A(a);
        // prefetch NEXT group's STE_Q during phase C MMAs
        {
            const bool validn = (node + 6 < Nn) && (g + 1 < NG);
#pragma unroll
            for (int i = 0; i < 6; i++) {
                if (validn) {
                    const float4 v = *(const float4*)(STE_Q + gof[i] + 384);
                    hx[i].x = ph2(v.x, v.y);
                    hx[i].y = ph2(v.z, v.w);
                }
            }
        }
#pragma unroll
        for (int mt = 0; mt < 4; mt++) {
            const float bj0 = sBias[128 + 16 * mt + gid];
            const float bj1 = sBias[128 + 16 * mt + 8 + gid];
            float d0[4] = {0.f, 0.f, 0.f, 0.f};
            float d1[4] = {0.f, 0.f, 0.f, 0.f};
#pragma unroll
            for (int kc = 0; kc < 4; kc++) {
                const int off = ((kc ^ g3) << 3) + 2 * tig;
                unsigned wa[4];
                ld_pair(sW + 2 * 2048 + (16 * mt + gid) * 32 + off, wa[0], wa[2]);
                ld_pair(sW + 2 * 2048 + (16 * mt + 8 + gid) * 32 + off, wa[1], wa[3]);
                mma16(d0, wa, a[kc][0], a[kc][2]);
                mma16(d1, wa, a[kc][1], a[kc][3]);
            }
            vb[2 * mt][0]     = ph2(fmaxf(d0[0] + bj0, 0.f), fmaxf(d0[1] + bj0, 0.f));
            vb[2 * mt][1]     = ph2(fmaxf(d1[0] + bj0, 0.f), fmaxf(d1[1] + bj0, 0.f));
            vb[2 * mt + 1][0] = ph2(fmaxf(d0[2] + bj1, 0.f), fmaxf(d0[3] + bj1, 0.f));
            vb[2 * mt + 1][1] = ph2(fmaxf(d1[2] + bj1, 0.f), fmaxf(d1[3] + bj1, 0.f));
        }
        __syncwarp();                                    // slab reads done
        // stage next group's STE_Q (warp-local rows)
        if ((node + 6 < Nn) && (g + 1 < NG)) { STS_IN(); }
        __syncwarp();

        // ---- attention: per head, all in registers ----
#pragma unroll
        for (int h = 0; h < 8; h++) {
            float s1[4] = {0.f, 0.f, 0.f, 0.f};
            float s2[4] = {0.f, 0.f, 0.f, 0.f};
            mma8(s1, qa[h][0], qa[h][1], kb[h][0]);      // p = 0..7
            mma8(s2, qa[h][0], qa[h][1], kb[h][1]);      // p = 8..15 (12-15 masked)
            const float e10 = __expf(s1[0] - 8.f), e11 = __expf(s1[1] - 8.f);
            const float e12 = __expf(s1[2] - 8.f), e13 = __expf(s1[3] - 8.f);
            float e20 = 0.f, e21 = 0.f, e22 = 0.f, e23 = 0.f;
            if (tig < 2) {                               // p = 8+2tig < 12
                e20 = __expf(s2[0] - 8.f); e21 = __expf(s2[1] - 8.f);
                e22 = __expf(s2[2] - 8.f); e23 = __expf(s2[3] - 8.f);
            }
            float sumA = e10 + e11 + e20 + e21;
            float sumB = e12 + e13 + e22 + e23;
            sumA += __shfl_xor_sync(0xffffffffu, sumA, 1);
            sumA += __shfl_xor_sync(0xffffffffu, sumA, 2);
            sumB += __shfl_xor_sync(0xffffffffu, sumB, 1);
            sumB += __shfl_xor_sync(0xffffffffu, sumB, 2);
            const float invA = __fdividef(1.f, sumA);
            const float invB = __fdividef(1.f, sumB);
            unsigned pa[4];
            pa[0] = ph2(e10 * invA, e11 * invA);
            pa[1] = ph2(e12 * invB, e13 * invB);
            pa[2] = ph2(e20 * invA, e21 * invA);
            pa[3] = ph2(e22 * invB, e23 * invB);
            float ov[4] = {0.f, 0.f, 0.f, 0.f};
            mma16(ov, pa, vb[h][0], vb[h][1]);
            oa[h][0] = ph2(ov[0], ov[1]);
            oa[h][1] = ph2(ov[2], ov[3]);
        }

        // ---- phase D: H = relu(attn @ W24^T + b24) -> ha regs ----
#pragma unroll
        for (int nt = 0; nt < 8; nt++) {
            float dd[4] = {0.f, 0.f, 0.f, 0.f};
            GEMM_REG(3, oa, nt, dd);
            const float2 bc = *(const float2*)(sBias + 192 + nt * 8 + 2 * tig);
            ha[nt][0] = ph2(fmaxf(dd[0] + bc.x, 0.f), fmaxf(dd[1] + bc.y, 0.f));
            ha[nt][1] = ph2(fmaxf(dd[2] + bc.x, 0.f), fmaxf(dd[3] + bc.y, 0.f));
        }

        // ---- phase E: out = H @ W25^T + b25 -> global ----
        {
            float* o0 = Out + ((size_t)(b * 12 + gid) * Nn + node) * 64;
            float* o1 = Out + ((size_t)(b * 12 + gid + 8) * Nn + node) * 64;
#pragma unroll
            for (int nt = 0; nt < 8; nt++) {
                float dd[4] = {0.f, 0.f, 0.f, 0.f};
                GEMM_REG(4, ha, nt, dd);
                const float2 bc = *(const float2*)(sBias + 256 + nt * 8 + 2 * tig);
                if (valid) {
                    *(float2*)(o0 + nt * 8 + 2 * tig) =
                        make_float2(dd[0] + bc.x, dd[1] + bc.y);
                    if (gid < 4)
                        *(float2*)(o1 + nt * 8 + 2 * tig) =
                            make_float2(dd[2] + bc.x, dd[3] + bc.y);
                }
            }
        }

        // advance to next group (node += 6 -> +384 floats)
#pragma unroll
        for (int i = 0; i < 6; i++) gof[i] += 384;
    }
#undef PREFETCH_AT
#undef STS_IN
#undef LOAD_A
#undef GEMM_PACK
#undef GEMM_REG
}

extern "C" void kernel_launch(void* const* d_in, const int* in_sizes, int n_in,
                              void* d_out, int out_size)
{
    const float* X     = (const float*)d_in[0];
    const float* STE_P = (const float*)d_in[1];
    const float* STE_Q = (const float*)d_in[2];
    const float* W21   = (const float*)d_in[3];
    const float* b21   = (const float*)d_in[4];
    const float* W22   = (const float*)d_in[5];
    const float* b22   = (const float*)d_in[6];
    const float* W23   = (const float*)d_in[7];
    const float* b23   = (const float*)d_in[8];
    const float* W24   = (const float*)d_in[9];
    const float* b24   = (const float*)d_in[10];
    const float* W25   = (const float*)d_in[11];
    const float* b25   = (const float*)d_in[12];
    float* Out = (float*)d_out;

    const size_t smem_bytes = (size_t)U_TOT * 4;          // 54,528 B -> 3 CTAs/SM

    cudaFuncSetAttribute(fused_reg_kernel,
                         cudaFuncAttributeMaxDynamicSharedMemorySize,
                         (int)smem_bytes);

    dim3 grid((Nn + NODES - 1) / NODES, Bsz);             // (167, 8) = 1336 CTAs
    fused_reg_kernel<<<grid, THREADS, smem_bytes>>>(
        X, STE_P, STE_Q,
        W21, b21, W22, b22, W23, b23, W24, b24, W25, b25,
        Out);
}